// round 1
// baseline (speedup 1.0000x reference)
#include <cuda_runtime.h>
#include <cstdint>

#define N_ANCH   100800
#define D_COLS   117
#define NC       80
#define NM       32
#define TOPK     4096
#define MAX_DET  300
#define CONF_T   0.25f
#define IOU_T    0.45f
#define CAND_CAP 8192

// ---------------- scratch (static __device__ — no allocation) ----------------
__device__ float              g_score[N_ANCH];   // masked scores (scores_m)
__device__ float              g_cls[N_ANCH];     // argmax class as float
__device__ unsigned int       g_hist[65536];
__device__ unsigned int       g_thresh_bucket;   // T
__device__ unsigned int       g_ncand;
__device__ unsigned long long g_cand[CAND_CAP];
__device__ int                g_top_idx[TOPK];
__device__ float              g_top_s[TOPK];
__device__ float              g_by1[TOPK], g_bx1[TOPK], g_by2[TOPK], g_bx2[TOPK];
__device__ int                g_out_pos[MAX_DET];
__device__ unsigned char      g_out_keep[MAX_DET];

// ---------------- helpers ----------------
__device__ __forceinline__ unsigned int f2key(float f) {
    unsigned int b = __float_as_uint(f);
    return b ^ ((b >> 31) ? 0xFFFFFFFFu : 0x80000000u);
}
__device__ __forceinline__ float key2f(unsigned int k) {
    unsigned int b = (k & 0x80000000u) ? (k ^ 0x80000000u) : ~k;
    return __uint_as_float(b);
}

// ---------------- k0: zero scratch ----------------
__global__ void k_zero() {
    int i = blockIdx.x * blockDim.x + threadIdx.x;
    for (int j = i; j < 65536; j += gridDim.x * blockDim.x) g_hist[j] = 0u;
    if (i == 0) g_ncand = 0u;
}

// ---------------- k1: per-anchor score/class + histogram (warp per anchor) ----
__global__ void k_score(const float* __restrict__ x) {
    int warp = (blockIdx.x * blockDim.x + threadIdx.x) >> 5;
    int lane = threadIdx.x & 31;
    if (warp >= N_ANCH) return;
    const float* row = x + (size_t)warp * D_COLS;
    float obj = row[4];

    float best = -1.0f; int bc = NC;
#pragma unroll
    for (int k = 0; k < 3; k++) {
        int c = lane + 32 * k;
        if (c < NC) {
            float v = __fmul_rn(row[5 + c], obj);
            if (v > best) { best = v; bc = c; }   // strict > : first index wins
        }
    }
    // warp argmax, tie -> smaller class index (matches jnp.argmax)
#pragma unroll
    for (int off = 16; off; off >>= 1) {
        float ov = __shfl_down_sync(0xFFFFFFFFu, best, off);
        int   oc = __shfl_down_sync(0xFFFFFFFFu, bc,   off);
        if (ov > best || (ov == best && oc < bc)) { best = ov; bc = oc; }
    }
    if (lane == 0) {
        float s = (obj > CONF_T) ? best : -1.0f;
        g_score[warp] = s;
        g_cls[warp]   = (float)bc;
        atomicAdd(&g_hist[f2key(s) >> 16], 1u);
    }
}

// ---------------- k2: find threshold bucket (single block) ----------------
__global__ void k_thresh() {
    __shared__ unsigned int partial[1024];
    __shared__ int          s_seg;
    __shared__ unsigned int s_before;
    int t = threadIdx.x;
    // thread t covers buckets [65536-64*(t+1), 65536-64*t) (descending segments)
    unsigned int s = 0;
    int hi = 65536 - 64 * t;
    for (int b = hi - 64; b < hi; b++) s += g_hist[b];
    partial[t] = s;
    __syncthreads();
    if (t == 0) {
        unsigned int cum = 0; int seg = 1023; unsigned int before = 0;
        for (int i = 0; i < 1024; i++) {
            if (cum + partial[i] >= TOPK) { seg = i; before = cum; break; }
            cum += partial[i];
        }
        s_seg = seg; s_before = before;
    }
    __syncthreads();
    if (t == s_seg) {
        unsigned int cum = s_before;
        int hi2 = 65536 - 64 * t;
        int T = hi2 - 64;
        for (int b = hi2 - 1; b >= hi2 - 64; b--) {
            unsigned int c = g_hist[b];
            if (cum + c >= TOPK) { T = b; break; }
            cum += c;
        }
        g_thresh_bucket = (unsigned int)T;
    }
}

// ---------------- k3: compact candidates ----------------
__global__ void k_compact() {
    int i = blockIdx.x * blockDim.x + threadIdx.x;
    if (i >= N_ANCH) return;
    unsigned int k = f2key(g_score[i]);
    if ((k >> 16) >= g_thresh_bucket) {
        unsigned int pos = atomicAdd(&g_ncand, 1u);
        if (pos < CAND_CAP)
            g_cand[pos] = ((unsigned long long)k << 32) | (unsigned int)(~i);
    }
}

// ---------------- k4: rank candidates -> sorted top-4096 ----------------
__global__ void k_rank() {
    __shared__ unsigned long long tile[256];
    int i = blockIdx.x * 256 + threadIdx.x;
    unsigned int n = g_ncand; if (n > CAND_CAP) n = CAND_CAP;
    unsigned long long my = (i < (int)n) ? g_cand[i] : 0ULL;
    int rank = 0;
    for (unsigned int base = 0; base < n; base += 256) {
        unsigned int idx = base + threadIdx.x;
        tile[threadIdx.x] = (idx < n) ? g_cand[idx] : 0ULL;
        __syncthreads();
        unsigned int lim = (n - base < 256u) ? (n - base) : 256u;
        for (unsigned int k = 0; k < lim; k++) rank += (tile[k] > my);
        __syncthreads();
    }
    if (i < (int)n && rank < TOPK) {
        g_top_s[rank]   = key2f((unsigned int)(my >> 32));
        g_top_idx[rank] = (int)(~(unsigned int)my);
    }
}

// ---------------- k5: gather boxes of the top-4096 ----------------
__global__ void k_gather(const float* __restrict__ x) {
    int i = blockIdx.x * blockDim.x + threadIdx.x;
    if (i >= TOPK) return;
    const float* row = x + (size_t)g_top_idx[i] * D_COLS;
    float xc = row[0], yc = row[1], w = row[2], h = row[3];
    float hh = __fmul_rn(h, 0.5f), hw = __fmul_rn(w, 0.5f);
    g_by1[i] = __fsub_rn(yc, hh);
    g_bx1[i] = __fsub_rn(xc, hw);
    g_by2[i] = __fadd_rn(yc, hh);
    g_bx2[i] = __fadd_rn(xc, hw);
}

// ---------------- k6: sequential greedy NMS (single block, 512 thr) ----------
__global__ void __launch_bounds__(512, 1) k_nms() {
    __shared__ unsigned int remv[128];   // 4096 removed-bits
    __shared__ float        stg[5];      // broadcast box i
    int t = threadIdx.x;

    // boxes register-resident: thread t owns j = t + 512*s, s in [0,8)
    float ry1[8], rx1[8], ry2[8], rx2[8], rar[8];
#pragma unroll
    for (int s = 0; s < 8; s++) {
        int j = t + (s << 9);
        float y1 = g_by1[j], x1 = g_bx1[j], y2 = g_by2[j], x2 = g_bx2[j];
        ry1[s] = y1; rx1[s] = x1; ry2[s] = y2; rx2[s] = x2;
        rar[s] = __fmul_rn(__fsub_rn(y2, y1), __fsub_rn(x2, x1));
    }
    if (t < 128) remv[t] = 0u;
    __syncthreads();
#pragma unroll
    for (int s = 0; s < 8; s++) {
        int j = t + (s << 9);
        if (!(g_top_s[j] > -0.5f)) atomicOr(&remv[j >> 5], 1u << (j & 31)); // keep0
    }
    __syncthreads();

    for (int w = 0; w < 128; w++) {
        unsigned int cur  = remv[w];
        unsigned int pend = ~cur;
        while (pend) {
            int b = __ffs(pend) - 1;
            pend &= pend - 1;
            if (cur & (1u << b)) continue;          // suppressed meanwhile
            int i = (w << 5) | b;                   // kept box -> suppress others
            if (t == (i & 511)) {
                int si = i >> 9;
#pragma unroll
                for (int s = 0; s < 8; s++)
                    if (s == si) { stg[0] = ry1[s]; stg[1] = rx1[s]; stg[2] = ry2[s]; stg[3] = rx2[s]; stg[4] = rar[s]; }
            }
            __syncthreads();
            float iy1 = stg[0], ix1 = stg[1], iy2 = stg[2], ix2 = stg[3], ia = stg[4];
#pragma unroll
            for (int s = 0; s < 8; s++) {
                int j = t + (s << 9);
                if (j > i) {
                    float yy1 = fmaxf(iy1, ry1[s]);
                    float xx1 = fmaxf(ix1, rx1[s]);
                    float yy2 = fminf(iy2, ry2[s]);
                    float xx2 = fminf(ix2, rx2[s]);
                    float dh  = fmaxf(__fsub_rn(yy2, yy1), 0.0f);
                    float dw  = fmaxf(__fsub_rn(xx2, xx1), 0.0f);
                    float it  = __fmul_rn(dh, dw);
                    float un  = __fsub_rn(__fadd_rn(ia, rar[s]), it);
                    float iou = __fdiv_rn(it, fmaxf(un, 1e-9f));
                    if (iou > IOU_T) atomicOr(&remv[j >> 5], 1u << (j & 31));
                }
            }
            __syncthreads();
            cur   = remv[w];
            pend &= ~cur;
        }
    }
    __syncthreads();

    // selection: first MAX_DET kept positions (ascending == value-desc order),
    // then pad with non-kept positions ascending (reference top_k on -1 ties)
    if (t == 0) {
        int cnt = 0;
        for (int w = 0; w < 128 && cnt < MAX_DET; w++) {
            unsigned int alive = ~remv[w];
            while (alive && cnt < MAX_DET) {
                int b = __ffs(alive) - 1; alive &= alive - 1;
                g_out_pos[cnt] = (w << 5) | b; g_out_keep[cnt] = 1; cnt++;
            }
        }
        for (int w = 0; w < 128 && cnt < MAX_DET; w++) {
            unsigned int dead = remv[w];
            while (dead && cnt < MAX_DET) {
                int b = __ffs(dead) - 1; dead &= dead - 1;
                g_out_pos[cnt] = (w << 5) | b; g_out_keep[cnt] = 0; cnt++;
            }
        }
    }
}

// ---------------- k7: final gather -> d_out (warp per detection) -------------
__global__ void k_out(const float* __restrict__ x, float* __restrict__ out) {
    int warp = (blockIdx.x * blockDim.x + threadIdx.x) >> 5;
    int lane = threadIdx.x & 31;
    if (warp >= MAX_DET) return;
    int pos = g_out_pos[warp];
    int a   = g_top_idx[pos];
    const float* row = x + (size_t)a * D_COLS;
    if (lane == 0) {
        float xc = row[0], yc = row[1], w = row[2], h = row[3];
        float hh = __fmul_rn(h, 0.5f), hw = __fmul_rn(w, 0.5f);
        out[warp * 4 + 0] = __fsub_rn(yc, hh);
        out[warp * 4 + 1] = __fsub_rn(xc, hw);
        out[warp * 4 + 2] = __fadd_rn(yc, hh);
        out[warp * 4 + 3] = __fadd_rn(xc, hw);
        out[MAX_DET * 4 + warp]     = g_cls[a];                          // classes
        out[MAX_DET * 5 + warp]     = g_out_keep[warp] ? g_top_s[pos] : -1.0f; // scores
    }
    out[MAX_DET * 6 + warp * NM + lane] = row[5 + NC + lane];            // masks
}

// ---------------- launch ----------------
extern "C" void kernel_launch(void* const* d_in, const int* in_sizes, int n_in,
                              void* d_out, int out_size) {
    const float* x = (const float*)d_in[0];
    float* out = (float*)d_out;

    k_zero   <<<64, 1024>>>();
    k_score  <<<(N_ANCH * 32 + 255) / 256, 256>>>(x);
    k_thresh <<<1, 1024>>>();
    k_compact<<<(N_ANCH + 255) / 256, 256>>>();
    k_rank   <<<CAND_CAP / 256, 256>>>();
    k_gather <<<TOPK / 256, 256>>>(x);
    k_nms    <<<1, 512>>>();
    k_out    <<<(MAX_DET * 32 + 255) / 256, 256>>>(x, out);
}